// round 16
// baseline (speedup 1.0000x reference)
#include <cuda_runtime.h>
#include <cuda_fp16.h>
#include <cstdint>

#define NN 24576
#define NE 98304
#define NG 512
#define NB 512
#define LL 1000

// ---------------- scratch (device globals; runtime alloc forbidden) ----------------
__device__ float g_h1[NN*128];
__device__ float g_as1[NN*2];
__device__ float g_ad1[NN*2];
__device__ float g_den1[NN*2];
__device__ float g_e1[(NE+NN)*2];
__device__ float g_out1[NN*128];
__device__ float g_h2[NN*128];
__device__ float g_as2[NN];
__device__ float g_ad2[NN];
__device__ float g_den2[NN];
__device__ float g_e2[NE+NN];
__device__ float g_out2[NN*128];
__device__ float g_sums[NG*128];
__device__ float g_cnt[NG];
__device__ float g_drug[NG*256];
__device__ float g_T[3*22*64];
__device__ __half g_p1h[NB*LL*64];   // conv1 output (fp16), [b][l][i]
__device__ float g_pmax[NB*128];
__device__ float g_prot[NB*256];

// ---------------- helpers ----------------
__device__ __forceinline__ void red_add_v4(float* addr, float4 v) {
    asm volatile("red.global.add.v4.f32 [%0], {%1, %2, %3, %4};"
                 :: "l"(addr), "f"(v.x), "f"(v.y), "f"(v.z), "f"(v.w) : "memory");
}
__device__ __forceinline__ void atomicMaxFloat(float* addr, float val) {
    if (val >= 0.f) atomicMax((int*)addr, __float_as_int(val));
    else            atomicMin((unsigned int*)addr, __float_as_uint(val));
}
__device__ __forceinline__ float warp_sum(float v) {
    #pragma unroll
    for (int off = 16; off; off >>= 1) v += __shfl_down_sync(0xffffffffu, v, off);
    return v;
}
__device__ __forceinline__ float elu1(float v) { return v > 0.f ? v : expm1f(v); }

__device__ __forceinline__ void mma_fp16(float* c, const uint32_t* a, const uint32_t* b) {
    asm volatile(
        "mma.sync.aligned.m16n8k16.row.col.f32.f16.f16.f32 "
        "{%0,%1,%2,%3}, {%4,%5,%6,%7}, {%8,%9}, {%0,%1,%2,%3};"
        : "+f"(c[0]), "+f"(c[1]), "+f"(c[2]), "+f"(c[3])
        : "r"(a[0]), "r"(a[1]), "r"(a[2]), "r"(a[3]), "r"(b[0]), "r"(b[1]));
}
__device__ __forceinline__ void ldsm_x4(uint32_t* r, uint32_t addr) {
    asm volatile("ldmatrix.sync.aligned.m8n8.x4.shared.b16 {%0,%1,%2,%3}, [%4];"
                 : "=r"(r[0]), "=r"(r[1]), "=r"(r[2]), "=r"(r[3]) : "r"(addr));
}
__device__ __forceinline__ uint32_t smem_u32(const void* p) {
    uint32_t a;
    asm("{ .reg .u64 t; cvta.to.shared.u64 t, %1; cvt.u32.u64 %0, t; }" : "=r"(a) : "l"(p));
    return a;
}

// ---------------- conv2: fp16 HMMA, M-split 2 CTAs/SM, double-buffered A ----------------
// Chunked launches: each covers work in [work_lo, work_hi) so higher-priority
// drug kernels interleave at chunk boundaries (persistent CTAs can't be preempted).
#define C2_A0 0
#define C2_A1 9792
#define C2_B  19584
#define C2_B_STRIDE 328
#define C2_SMEM 103552
#define C2_WORK (NB*8*2)

__global__ void __launch_bounds__(256) k_conv2_hmma(const float* __restrict__ K2,
                                                    const float* __restrict__ bk2,
                                                    int work_lo, int work_hi) {
    extern __shared__ char smem[];
    __half* BhS = reinterpret_cast<__half*>(smem + C2_B);

    int tid = threadIdx.x, wid = tid >> 5, lane = tid & 31;
    int g = lane >> 2, q = lane & 3;
    int mw2 = (wid & 1) * 32;
    int nw4 = (wid >> 1) * 32;
    int m_base = (blockIdx.x & 1) * 64;   // == (work & 1)*64 since work_lo, gridDim even

    uint32_t sb = smem_u32(smem);
    uint32_t sbB = sb + C2_B;

    uint32_t aoff = (uint32_t)(lane & 15) * 144u + ((lane & 16) ? 16u : 0u);
    uint32_t boff = (uint32_t)(lane & 7) * 656u + ((lane & 8) ? 16u : 0u)
                  + ((lane & 16) ? 8u*656u : 0u);

    for (int idx = tid; idx < 128*320; idx += 256) {
        int n = idx / 320, k = idx - n*320;
        int t = k >> 6, i = k & 63;
        BhS[n*C2_B_STRIDE + k] = __float2half_rn(K2[(n*64 + i)*5 + t]);
    }

    float bias[4][2];
    #pragma unroll
    for (int nt = 0; nt < 4; nt++) {
        int col = nw4 + nt*8 + q*2;
        bias[nt][0] = bk2[col];
        bias[nt][1] = bk2[col + 1];
    }

    auto issue_A = [&](int work_, int buf_) {
        int tile_ = work_ >> 1;
        int b_ = tile_ >> 3;
        int lbase = (tile_ & 7) * 125 + m_base - 2;
        uint32_t sbA_ = sb + (buf_ ? C2_A1 : C2_A0);
        for (int idx = tid; idx < 544; idx += 256) {
            int row = idx >> 3, c = idx & 7;
            int l = lbase + row;
            int lc = l < 0 ? 0 : (l >= LL ? LL-1 : l);
            const __half* gsrc = g_p1h + ((size_t)b_*LL + lc)*64 + c*8;
            uint32_t dst = sbA_ + (uint32_t)(row*144 + c*16);
            int sz = (l >= 0 && l < LL) ? 16 : 0;
            asm volatile("cp.async.cg.shared.global [%0], [%1], 16, %2;"
                         :: "r"(dst), "l"(gsrc), "r"(sz));
        }
        asm volatile("cp.async.commit_group;" ::: "memory");
    };

    int first = work_lo + blockIdx.x;
    if (first < work_hi) issue_A(first, 0);
    int p = 0;
    for (int work = first; work < work_hi; work += gridDim.x) {
        int tile = work >> 1;
        int b = tile >> 3, l0 = (tile & 7) * 125;
        int nxt = work + gridDim.x;
        if (nxt < work_hi) {
            issue_A(nxt, p ^ 1);
            asm volatile("cp.async.wait_group 1;" ::: "memory");
        } else {
            asm volatile("cp.async.wait_group 0;" ::: "memory");
        }
        __syncthreads();
        uint32_t sbA = sb + (p ? C2_A1 : C2_A0);

        float acc[2][4][4];
        #pragma unroll
        for (int mt = 0; mt < 2; mt++)
            #pragma unroll
            for (int nt = 0; nt < 4; nt++)
                #pragma unroll
                for (int j = 0; j < 4; j++) acc[mt][nt][j] = 0.f;

        #pragma unroll
        for (int ks = 0; ks < 20; ks++) {
            int t = ks >> 2;
            uint32_t kb = (uint32_t)((ks & 3) * 32);
            uint32_t ah[2][4], bb[2][4];
            uint32_t aBase = (uint32_t)((mw2 + t) * 144) + kb + aoff;
            #pragma unroll
            for (int mt = 0; mt < 2; mt++)
                ldsm_x4(ah[mt], sbA + aBase + (uint32_t)(mt*16*144));
            uint32_t bBase = (uint32_t)(nw4 * 656) + (uint32_t)(t * 128) + kb + boff;
            #pragma unroll
            for (int np = 0; np < 2; np++)
                ldsm_x4(bb[np], sbB + bBase + (uint32_t)(np*16*656));
            #pragma unroll
            for (int mt = 0; mt < 2; mt++)
                #pragma unroll
                for (int nt = 0; nt < 4; nt++)
                    mma_fp16(acc[mt][nt], ah[mt], &bb[nt >> 1][(nt & 1)*2]);
        }
        __syncthreads();   // all threads done reading buf p

        // epilogue: raw max over valid l, elu applied once (monotonic)
        float mx[4][2];
        #pragma unroll
        for (int nt = 0; nt < 4; nt++) { mx[nt][0] = -3.0e38f; mx[nt][1] = -3.0e38f; }
        #pragma unroll
        for (int mt = 0; mt < 2; mt++) {
            int lr = l0 + m_base + mw2 + mt*16 + g;
            bool v0 = lr < LL, v1 = (lr + 8) < LL;
            #pragma unroll
            for (int nt = 0; nt < 4; nt++) {
                if (v0) {
                    mx[nt][0] = fmaxf(mx[nt][0], acc[mt][nt][0]);
                    mx[nt][1] = fmaxf(mx[nt][1], acc[mt][nt][1]);
                }
                if (v1) {
                    mx[nt][0] = fmaxf(mx[nt][0], acc[mt][nt][2]);
                    mx[nt][1] = fmaxf(mx[nt][1], acc[mt][nt][3]);
                }
            }
        }
        #pragma unroll
        for (int nt = 0; nt < 4; nt++) {
            #pragma unroll
            for (int j = 0; j < 2; j++) {
                float v = mx[nt][j];
                v = fmaxf(v, __shfl_xor_sync(0xffffffffu, v, 4));
                v = fmaxf(v, __shfl_xor_sync(0xffffffffu, v, 8));
                v = fmaxf(v, __shfl_xor_sync(0xffffffffu, v, 16));
                if (lane < 4)
                    atomicMaxFloat(&g_pmax[b*128 + nw4 + nt*8 + lane*2 + j],
                                   elu1(v + bias[nt][j]));
            }
        }
        p ^= 1;
    }
}

// ---------------- conv1 token tables ----------------
__global__ void k_tab(const float* __restrict__ Pe, const float* __restrict__ K1,
                      const float* __restrict__ bk1) {
    int idx = blockIdx.x * blockDim.x + threadIdx.x;
    if (idx >= 3*22*64) return;
    int o = idx & 63, r = idx >> 6;
    int t = r % 22, k = r / 22;
    float acc = (k == 1) ? bk1[o] : 0.f;
    #pragma unroll 8
    for (int i = 0; i < 64; i++) acc += Pe[t*64 + i] * K1[(o*64 + i)*3 + k];
    g_T[idx] = acc;
}

// ---------------- conv1 apply: writes fp16 directly ----------------
__global__ void __launch_bounds__(256) k_conv1_apply(const int* __restrict__ seq) {
    int b = blockIdx.y;
    int lofs = threadIdx.x >> 4, lq = threadIdx.x & 15;
    int l = blockIdx.x * 16 + lofs;
    if (l >= LL) return;
    int s1 = seq[b*LL + l];
    int c = lq * 4;
    float4 v = *reinterpret_cast<const float4*>(&g_T[(22 + s1)*64 + c]);
    if (l > 0) {
        int s0 = seq[b*LL + l - 1];
        float4 a = *reinterpret_cast<const float4*>(&g_T[s0*64 + c]);
        v.x += a.x; v.y += a.y; v.z += a.z; v.w += a.w;
    }
    if (l < LL-1) {
        int s2 = seq[b*LL + l + 1];
        float4 a = *reinterpret_cast<const float4*>(&g_T[(44 + s2)*64 + c]);
        v.x += a.x; v.y += a.y; v.z += a.z; v.w += a.w;
    }
    __half2 h0 = __floats2half2_rn(elu1(v.x), elu1(v.y));
    __half2 h1 = __floats2half2_rn(elu1(v.z), elu1(v.w));
    size_t base = ((size_t)b*LL + l)*64 + c;
    *reinterpret_cast<__half2*>(&g_p1h[base])     = h0;
    *reinterpret_cast<__half2*>(&g_p1h[base + 2]) = h1;
}

// ---------------- init ----------------
__global__ void k_init_prot() {
    int i = blockIdx.x * blockDim.x + threadIdx.x;
    if (i < NB*128) g_pmax[i] = -3.0e38f;
}

// ---------------- GAT1 GEMM + fused attention scalars (warp per node) ----------------
__global__ void k_gat1(const float* __restrict__ x, const float* __restrict__ W1,
                       const float* __restrict__ att_s, const float* __restrict__ att_d) {
    int gw = (blockIdx.x * blockDim.x + threadIdx.x) >> 5;
    int lane = threadIdx.x & 31;
    if (gw >= NN) return;
    float xv[5];
    #pragma unroll
    for (int f = 0; f < 5; f++) xv[f] = x[gw*5 + f];
    int c = lane * 4;
    float4 h;
    float* hp = reinterpret_cast<float*>(&h);
    #pragma unroll
    for (int j = 0; j < 4; j++) {
        float a = 0.f;
        #pragma unroll
        for (int f = 0; f < 5; f++) a += xv[f] * W1[f*128 + c + j];
        hp[j] = a;
    }
    *reinterpret_cast<float4*>(&g_h1[(size_t)gw*128 + c]) = h;
    float s = 0.f, d = 0.f;
    #pragma unroll
    for (int j = 0; j < 4; j++) { s += hp[j]*att_s[c + j]; d += hp[j]*att_d[c + j]; }
    float s0 = (lane < 16) ? s : 0.f, s1 = (lane < 16) ? 0.f : s;
    float d0 = (lane < 16) ? d : 0.f, d1 = (lane < 16) ? 0.f : d;
    s0 = warp_sum(s0); s1 = warp_sum(s1); d0 = warp_sum(d0); d1 = warp_sum(d1);
    if (lane == 0) {
        g_as1[gw*2] = s0; g_as1[gw*2+1] = s1;
        g_ad1[gw*2] = d0; g_ad1[gw*2+1] = d1;
    }
}

// ---------------- edge passes (softmax without max-shift: scores are O(1)) ----------------
template<int H>
__global__ void k_edge_den(const int* __restrict__ ei) {
    int e = blockIdx.x * blockDim.x + threadIdx.x;
    const int ET = NE + NN;
    if (e >= ET) return;
    int src, dst;
    if (e < NE) { src = ei[e]; dst = ei[NE + e]; } else { src = dst = e - NE; }
    const float* as_ = (H == 2) ? g_as1 : g_as2;
    const float* ad_ = (H == 2) ? g_ad1 : g_ad2;
    float* den_ = (H == 2) ? g_den1 : g_den2;
    float* e_ = (H == 2) ? g_e1 : g_e2;
    #pragma unroll
    for (int h = 0; h < H; h++) {
        float v = as_[src*H+h] + ad_[dst*H+h];
        v = v > 0.f ? v : 0.2f * v;
        float w = expf(v);
        e_[e*H+h] = w;
        atomicAdd(&den_[dst*H+h], w);
    }
}

template<int H>
__global__ void k_edge_acc(const int* __restrict__ ei) {
    int gw = (blockIdx.x * blockDim.x + threadIdx.x) >> 5;
    int lane = threadIdx.x & 31;
    const int ET = NE + NN;
    if (gw >= ET) return;
    int src, dst;
    if (gw < NE) { src = ei[gw]; dst = ei[NE + gw]; } else { src = dst = gw - NE; }
    const float* den_ = (H == 2) ? g_den1 : g_den2;
    const float* e_ = (H == 2) ? g_e1 : g_e2;
    const float* hin = (H == 2) ? g_h1 : g_h2;
    float* outp = (H == 2) ? g_out1 : g_out2;
    int h = (H == 2 && lane >= 16) ? 1 : 0;
    float alpha = e_[gw*H + h] / (den_[dst*H + h] + 1e-16f);
    float4 v = *reinterpret_cast<const float4*>(&hin[(size_t)src*128 + lane*4]);
    v.x *= alpha; v.y *= alpha; v.z *= alpha; v.w *= alpha;
    red_add_v4(&outp[(size_t)dst*128 + lane*4], v);
}

// ---------------- GAT2 GEMM (bias1+elu fused on A-load; att2 fused in epilogue) ----------------
__global__ void __launch_bounds__(256) k_gat2_mm(const float* __restrict__ W2,
                                                 const float* __restrict__ b1,
                                                 const float* __restrict__ att_s,
                                                 const float* __restrict__ att_d) {
    extern __shared__ float sm[];
    float* sg = sm;
    float* sw = sm + 64*128;
    int base = blockIdx.x * 64;
    int tid = threadIdx.x;
    for (int idx = tid; idx < 64*128; idx += 256)
        sg[idx] = elu1(g_out1[(size_t)base*128 + idx] + b1[idx & 127]);
    for (int idx = tid; idx < 128*128; idx += 256) sw[idx] = W2[idx];
    __syncthreads();
    int r0 = (tid >> 4) << 2;
    int c0 = (tid & 15) << 3;
    float acc[4][8];
    #pragma unroll
    for (int i = 0; i < 4; i++)
        #pragma unroll
        for (int j = 0; j < 8; j++) acc[i][j] = 0.f;
    #pragma unroll 4
    for (int k = 0; k < 128; k++) {
        float a[4];
        #pragma unroll
        for (int i = 0; i < 4; i++) a[i] = sg[(r0+i)*128 + k];
        float4 b0 = *reinterpret_cast<const float4*>(&sw[k*128 + c0]);
        float4 b1v = *reinterpret_cast<const float4*>(&sw[k*128 + c0 + 4]);
        #pragma unroll
        for (int i = 0; i < 4; i++) {
            acc[i][0] += a[i]*b0.x; acc[i][1] += a[i]*b0.y;
            acc[i][2] += a[i]*b0.z; acc[i][3] += a[i]*b0.w;
            acc[i][4] += a[i]*b1v.x; acc[i][5] += a[i]*b1v.y;
            acc[i][6] += a[i]*b1v.z; acc[i][7] += a[i]*b1v.w;
        }
    }
    #pragma unroll
    for (int i = 0; i < 4; i++) {
        float4 v0 = make_float4(acc[i][0], acc[i][1], acc[i][2], acc[i][3]);
        float4 v1 = make_float4(acc[i][4], acc[i][5], acc[i][6], acc[i][7]);
        *reinterpret_cast<float4*>(&g_h2[(size_t)(base+r0+i)*128 + c0]) = v0;
        *reinterpret_cast<float4*>(&g_h2[(size_t)(base+r0+i)*128 + c0 + 4]) = v1;
    }
    float ps[4], pd[4];
    #pragma unroll
    for (int i = 0; i < 4; i++) {
        float s = 0.f, d = 0.f;
        #pragma unroll
        for (int j = 0; j < 8; j++) {
            s += acc[i][j] * att_s[c0 + j];
            d += acc[i][j] * att_d[c0 + j];
        }
        ps[i] = s; pd[i] = d;
    }
    #pragma unroll
    for (int i = 0; i < 4; i++) {
        #pragma unroll
        for (int off = 8; off; off >>= 1) {
            ps[i] += __shfl_down_sync(0xffffffffu, ps[i], off, 16);
            pd[i] += __shfl_down_sync(0xffffffffu, pd[i], off, 16);
        }
    }
    if ((tid & 15) == 0) {
        #pragma unroll
        for (int i = 0; i < 4; i++) {
            g_as2[base + r0 + i] = ps[i];
            g_ad2[base + r0 + i] = pd[i];
        }
    }
}

// ---------------- pooling (bias2+elu fused) + dense ----------------
__global__ void k_pool(const int* __restrict__ batch, const float* __restrict__ b2) {
    int gw = (blockIdx.x * blockDim.x + threadIdx.x) >> 5;
    int lane = threadIdx.x & 31;
    if (gw >= NN) return;
    int g = batch[gw];
    int c = lane * 4;
    float4 v = *reinterpret_cast<const float4*>(&g_out2[(size_t)gw*128 + c]);
    v.x = elu1(v.x + b2[c]);
    v.y = elu1(v.y + b2[c+1]);
    v.z = elu1(v.z + b2[c+2]);
    v.w = elu1(v.w + b2[c+3]);
    red_add_v4(&g_sums[g*128 + c], v);
    if (lane == 0) atomicAdd(&g_cnt[g], 1.0f);
}

__global__ void k_drug(const float* __restrict__ Wd, const float* __restrict__ bd) {
    int idx = blockIdx.x * blockDim.x + threadIdx.x;
    if (idx >= NG*64) return;
    int g = idx >> 6, j4 = (idx & 63) * 4;
    float invc = 1.f / fmaxf(g_cnt[g], 1.f);
    const float* srow = g_sums + g*128;
    float4 a = make_float4(0.f, 0.f, 0.f, 0.f);
    #pragma unroll 8
    for (int k = 0; k < 128; k++) {
        float s = srow[k];
        float4 w = *reinterpret_cast<const float4*>(&Wd[k*256 + j4]);
        a.x += s*w.x; a.y += s*w.y; a.z += s*w.z; a.w += s*w.w;
    }
    float4 r;
    r.x = fmaxf(a.x * invc + bd[j4],     0.f);
    r.y = fmaxf(a.y * invc + bd[j4 + 1], 0.f);
    r.z = fmaxf(a.z * invc + bd[j4 + 2], 0.f);
    r.w = fmaxf(a.w * invc + bd[j4 + 3], 0.f);
    *reinterpret_cast<float4*>(&g_drug[g*256 + j4]) = r;
}

__global__ void k_prot(const float* __restrict__ Wp, const float* __restrict__ bp) {
    int idx = blockIdx.x * blockDim.x + threadIdx.x;
    if (idx >= NB*64) return;
    int g = idx >> 6, j4 = (idx & 63) * 4;
    const float* srow = g_pmax + g*128;
    float4 a = make_float4(0.f, 0.f, 0.f, 0.f);
    #pragma unroll 8
    for (int k = 0; k < 128; k++) {
        float s = srow[k];
        float4 w = *reinterpret_cast<const float4*>(&Wp[k*256 + j4]);
        a.x += s*w.x; a.y += s*w.y; a.z += s*w.z; a.w += s*w.w;
    }
    float4 r;
    r.x = fmaxf(a.x + bp[j4],     0.f);
    r.y = fmaxf(a.y + bp[j4 + 1], 0.f);
    r.z = fmaxf(a.z + bp[j4 + 2], 0.f);
    r.w = fmaxf(a.w + bp[j4 + 3], 0.f);
    *reinterpret_cast<float4*>(&g_prot[g*256 + j4]) = r;
}

// ---------------- head MLP ----------------
__global__ void __launch_bounds__(128) k_head(const float* __restrict__ Wf1, const float* __restrict__ bf1,
                                              const float* __restrict__ Wf2, const float* __restrict__ bf2,
                                              const float* __restrict__ Wo, const float* __restrict__ bo,
                                              float* __restrict__ out) {
    __shared__ float sh[512];
    __shared__ float s1[128];
    __shared__ float s2[64];
    int g = blockIdx.x, tid = threadIdx.x;
    for (int i = tid; i < 256; i += 128) {
        sh[i]       = g_drug[g*256 + i];
        sh[256 + i] = g_prot[g*256 + i];
    }
    __syncthreads();
    float acc = 0.f;
    #pragma unroll 8
    for (int k = 0; k < 512; k++) acc += sh[k] * Wf1[k*128 + tid];
    s1[tid] = fmaxf(acc + bf1[tid], 0.f);
    __syncthreads();
    if (tid < 64) {
        float a = 0.f;
        #pragma unroll 8
        for (int k = 0; k < 128; k++) a += s1[k] * Wf2[k*64 + tid];
        s2[tid] = fmaxf(a + bf2[tid], 0.f);
    }
    __syncthreads();
    if (tid < 32) {
        float a = s2[tid]*Wo[tid] + s2[tid+32]*Wo[tid+32];
        a = warp_sum(a);
        if (tid == 0) out[g] = a + bo[0];
    }
}

// ---------------- launch: protein branch (chunked conv2) on low-priority stream ----------------
extern "C" void kernel_launch(void* const* d_in, const int* in_sizes, int n_in,
                              void* d_out, int out_size) {
    const float* x        = (const float*)d_in[0];
    const int*   ei       = (const int*)d_in[1];
    const int*   batch    = (const int*)d_in[2];
    const int*   seq      = (const int*)d_in[3];
    const float* W1       = (const float*)d_in[4];
    const float* att_s1   = (const float*)d_in[5];
    const float* att_d1   = (const float*)d_in[6];
    const float* b1       = (const float*)d_in[7];
    const float* W2       = (const float*)d_in[8];
    const float* att_s2   = (const float*)d_in[9];
    const float* att_d2   = (const float*)d_in[10];
    const float* b2       = (const float*)d_in[11];
    const float* Wd       = (const float*)d_in[12];
    const float* bd       = (const float*)d_in[13];
    const float* Pe       = (const float*)d_in[14];
    const float* K1       = (const float*)d_in[15];
    const float* bk1      = (const float*)d_in[16];
    const float* K2       = (const float*)d_in[17];
    const float* bk2      = (const float*)d_in[18];
    const float* Wp       = (const float*)d_in[19];
    const float* bp       = (const float*)d_in[20];
    const float* Wf1      = (const float*)d_in[21];
    const float* bf1      = (const float*)d_in[22];
    const float* Wf2      = (const float*)d_in[23];
    const float* bf2      = (const float*)d_in[24];
    const float* Wo       = (const float*)d_in[25];
    const float* bo       = (const float*)d_in[26];
    float* out = (float*)d_out;

    cudaFuncSetAttribute(k_gat2_mm,    cudaFuncAttributeMaxDynamicSharedMemorySize, 98304);
    cudaFuncSetAttribute(k_conv2_hmma, cudaFuncAttributeMaxDynamicSharedMemorySize, C2_SMEM);

    const int ET = NE + NN;

    int prLo = 0, prHi = 0;
    cudaDeviceGetStreamPriorityRange(&prLo, &prHi);
    cudaStream_t sp;
    cudaStreamCreateWithPriority(&sp, cudaStreamNonBlocking, prLo);  // protein = low priority
    cudaEvent_t e0, ep;
    cudaEventCreateWithFlags(&e0, cudaEventDisableTiming);
    cudaEventCreateWithFlags(&ep, cudaEventDisableTiming);

    cudaEventRecord(e0, 0);
    cudaStreamWaitEvent(sp, e0, 0);

    // ---- protein branch on sp ----
    k_init_prot<<<(NB*128 + 255)/256, 256, 0, sp>>>();
    k_tab<<<17, 256, 0, sp>>>(Pe, K1, bk1);
    {
        dim3 grid((LL + 15)/16, NB);
        k_conv1_apply<<<grid, 256, 0, sp>>>(seq);
    }
    for (int c = 0; c < 4; c++)
        k_conv2_hmma<<<296, 256, C2_SMEM, sp>>>(K2, bk2, c*(C2_WORK/4), (c+1)*(C2_WORK/4));
    k_prot<<<(NB*64 + 255)/256, 256, 0, sp>>>(Wp, bp);
    cudaEventRecord(ep, sp);

    // ---- drug branch on the default (capture) stream ----
    {
        void* p;
        cudaGetSymbolAddress(&p, g_out1);  cudaMemsetAsync(p, 0, sizeof(float)*NN*128, 0);
        cudaGetSymbolAddress(&p, g_out2);  cudaMemsetAsync(p, 0, sizeof(float)*NN*128, 0);
        cudaGetSymbolAddress(&p, g_den1);  cudaMemsetAsync(p, 0, sizeof(float)*NN*2, 0);
        cudaGetSymbolAddress(&p, g_den2);  cudaMemsetAsync(p, 0, sizeof(float)*NN, 0);
        cudaGetSymbolAddress(&p, g_sums);  cudaMemsetAsync(p, 0, sizeof(float)*NG*128, 0);
        cudaGetSymbolAddress(&p, g_cnt);   cudaMemsetAsync(p, 0, sizeof(float)*NG, 0);
    }
    k_gat1<<<(NN*32 + 255)/256, 256>>>(x, W1, att_s1, att_d1);
    k_edge_den<2><<<(ET + 255)/256, 256>>>(ei);
    k_edge_acc<2><<<(ET*32 + 255)/256, 256>>>(ei);
    k_gat2_mm<<<NN/64, 256, 98304>>>(W2, b1, att_s2, att_d2);
    k_edge_den<1><<<(ET + 255)/256, 256>>>(ei);
    k_edge_acc<1><<<(ET*32 + 255)/256, 256>>>(ei);
    k_pool<<<(NN*32 + 255)/256, 256>>>(batch, b2);
    k_drug<<<(NG*64 + 255)/256, 256>>>(Wd, bd);

    // join: head needs both branches
    cudaStreamWaitEvent(0, ep, 0);
    k_head<<<NG, 128>>>(Wf1, bf1, Wf2, bf2, Wo, bo, out);
}

// round 17
// speedup vs baseline: 1.1010x; 1.1010x over previous
#include <cuda_runtime.h>
#include <cuda_fp16.h>
#include <cstdint>

#define NN 24576
#define NE 98304
#define NG 512
#define NB 512
#define LL 1000

// ---------------- scratch (device globals; runtime alloc forbidden) ----------------
__device__ float g_h1[NN*128];
__device__ float g_as1[NN*2];
__device__ float g_ad1[NN*2];
__device__ float g_den1[NN*2];
__device__ float g_e1[(NE+NN)*2];
__device__ float g_out1[NN*128];
__device__ float g_h2[NN*128];
__device__ float g_as2[NN];
__device__ float g_ad2[NN];
__device__ float g_den2[NN];
__device__ float g_e2[NE+NN];
__device__ float g_out2[NN*128];
__device__ float g_sums[NG*128];
__device__ float g_cnt[NG];
__device__ float g_drug[NG*256];
__device__ float g_T[3*22*64];
__device__ __half g_p1h[NB*LL*64];     // conv1 output (fp16), [b][l][i]
__device__ __half g_Bh[128*328];       // conv2 weights, fp16, padded stride 328
__device__ float g_pmax[NB*128];
__device__ float g_prot[NB*256];

// ---------------- helpers ----------------
__device__ __forceinline__ void red_add_v4(float* addr, float4 v) {
    asm volatile("red.global.add.v4.f32 [%0], {%1, %2, %3, %4};"
                 :: "l"(addr), "f"(v.x), "f"(v.y), "f"(v.z), "f"(v.w) : "memory");
}
__device__ __forceinline__ void atomicMaxFloat(float* addr, float val) {
    if (val >= 0.f) atomicMax((int*)addr, __float_as_int(val));
    else            atomicMin((unsigned int*)addr, __float_as_uint(val));
}
__device__ __forceinline__ float warp_sum(float v) {
    #pragma unroll
    for (int off = 16; off; off >>= 1) v += __shfl_down_sync(0xffffffffu, v, off);
    return v;
}
__device__ __forceinline__ float elu1(float v) { return v > 0.f ? v : expm1f(v); }

__device__ __forceinline__ void mma_fp16(float* c, const uint32_t* a, const uint32_t* b) {
    asm volatile(
        "mma.sync.aligned.m16n8k16.row.col.f32.f16.f16.f32 "
        "{%0,%1,%2,%3}, {%4,%5,%6,%7}, {%8,%9}, {%0,%1,%2,%3};"
        : "+f"(c[0]), "+f"(c[1]), "+f"(c[2]), "+f"(c[3])
        : "r"(a[0]), "r"(a[1]), "r"(a[2]), "r"(a[3]), "r"(b[0]), "r"(b[1]));
}
__device__ __forceinline__ void ldsm_x4(uint32_t* r, uint32_t addr) {
    asm volatile("ldmatrix.sync.aligned.m8n8.x4.shared.b16 {%0,%1,%2,%3}, [%4];"
                 : "=r"(r[0]), "=r"(r[1]), "=r"(r[2]), "=r"(r[3]) : "r"(addr));
}
__device__ __forceinline__ uint32_t smem_u32(const void* p) {
    uint32_t a;
    asm("{ .reg .u64 t; cvta.to.shared.u64 t, %1; cvt.u32.u64 %0, t; }" : "=r"(a) : "l"(p));
    return a;
}

// ---------------- conv2 B pre-conversion (once, tiny) ----------------
__global__ void k_bconv(const float* __restrict__ K2) {
    int idx = blockIdx.x * blockDim.x + threadIdx.x;
    if (idx >= 128*320) return;
    int n = idx / 320, k = idx - n*320;
    int t = k >> 6, i = k & 63;
    g_Bh[n*328 + k] = __float2half_rn(K2[(n*64 + i)*5 + t]);
}

// ---------------- conv2: fp16 HMMA, M-split 2 CTAs/SM, double-buffered A ----------------
#define C2_A0 0
#define C2_A1 9792
#define C2_B  19584
#define C2_B_STRIDE 328
#define C2_SMEM 103552
#define C2_WORK (NB*8*2)

__global__ void __launch_bounds__(256) k_conv2_hmma(const float* __restrict__ bk2) {
    extern __shared__ char smem[];

    int tid = threadIdx.x, wid = tid >> 5, lane = tid & 31;
    int g = lane >> 2, q = lane & 3;
    int mw2 = (wid & 1) * 32;
    int nw4 = (wid >> 1) * 32;
    int m_base = (blockIdx.x & 1) * 64;

    uint32_t sb = smem_u32(smem);
    uint32_t sbB = sb + C2_B;

    uint32_t aoff = (uint32_t)(lane & 15) * 144u + ((lane & 16) ? 16u : 0u);
    uint32_t boff = (uint32_t)(lane & 7) * 656u + ((lane & 8) ? 16u : 0u)
                  + ((lane & 16) ? 8u*656u : 0u);

    // ---- B stage: flat 84KB cp.async from pre-converted g_Bh (group 0) ----
    {
        const char* bsrc = reinterpret_cast<const char*>(g_Bh);
        for (int idx = tid; idx < 5248; idx += 256) {
            asm volatile("cp.async.cg.shared.global [%0], [%1], 16;"
                         :: "r"(sbB + (uint32_t)(idx*16)), "l"(bsrc + idx*16));
        }
        asm volatile("cp.async.commit_group;" ::: "memory");
    }

    float bias[4][2];
    #pragma unroll
    for (int nt = 0; nt < 4; nt++) {
        int col = nw4 + nt*8 + q*2;
        bias[nt][0] = bk2[col];
        bias[nt][1] = bk2[col + 1];
    }

    auto issue_A = [&](int work_, int buf_) {
        int tile_ = work_ >> 1;
        int b_ = tile_ >> 3;
        int lbase = (tile_ & 7) * 125 + m_base - 2;
        uint32_t sbA_ = sb + (buf_ ? C2_A1 : C2_A0);
        for (int idx = tid; idx < 544; idx += 256) {
            int row = idx >> 3, c = idx & 7;
            int l = lbase + row;
            int lc = l < 0 ? 0 : (l >= LL ? LL-1 : l);
            const __half* gsrc = g_p1h + ((size_t)b_*LL + lc)*64 + c*8;
            uint32_t dst = sbA_ + (uint32_t)(row*144 + c*16);
            int sz = (l >= 0 && l < LL) ? 16 : 0;
            asm volatile("cp.async.cg.shared.global [%0], [%1], 16, %2;"
                         :: "r"(dst), "l"(gsrc), "r"(sz));
        }
        asm volatile("cp.async.commit_group;" ::: "memory");
    };

    issue_A(blockIdx.x, 0);               // group 1 (B is group 0; groups retire in order)
    int p = 0;
    for (int work = blockIdx.x; work < C2_WORK; work += gridDim.x) {
        int tile = work >> 1;
        int b = tile >> 3, l0 = (tile & 7) * 125;
        int nxt = work + gridDim.x;
        if (nxt < C2_WORK) {
            issue_A(nxt, p ^ 1);
            asm volatile("cp.async.wait_group 1;" ::: "memory");   // B + A(t) complete
        } else {
            asm volatile("cp.async.wait_group 0;" ::: "memory");
        }
        __syncthreads();
        uint32_t sbA = sb + (p ? C2_A1 : C2_A0);

        float acc[2][4][4];
        #pragma unroll
        for (int mt = 0; mt < 2; mt++)
            #pragma unroll
            for (int nt = 0; nt < 4; nt++)
                #pragma unroll
                for (int j = 0; j < 4; j++) acc[mt][nt][j] = 0.f;

        #pragma unroll
        for (int ks = 0; ks < 20; ks++) {
            int t = ks >> 2;
            uint32_t kb = (uint32_t)((ks & 3) * 32);
            uint32_t ah[2][4], bb[2][4];
            uint32_t aBase = (uint32_t)((mw2 + t) * 144) + kb + aoff;
            #pragma unroll
            for (int mt = 0; mt < 2; mt++)
                ldsm_x4(ah[mt], sbA + aBase + (uint32_t)(mt*16*144));
            uint32_t bBase = (uint32_t)(nw4 * 656) + (uint32_t)(t * 128) + kb + boff;
            #pragma unroll
            for (int np = 0; np < 2; np++)
                ldsm_x4(bb[np], sbB + bBase + (uint32_t)(np*16*656));
            #pragma unroll
            for (int mt = 0; mt < 2; mt++)
                #pragma unroll
                for (int nt = 0; nt < 4; nt++)
                    mma_fp16(acc[mt][nt], ah[mt], &bb[nt >> 1][(nt & 1)*2]);
        }
        __syncthreads();   // all threads done reading buf p

        // epilogue: raw max over valid l, elu applied once (monotonic)
        float mx[4][2];
        #pragma unroll
        for (int nt = 0; nt < 4; nt++) { mx[nt][0] = -3.0e38f; mx[nt][1] = -3.0e38f; }
        #pragma unroll
        for (int mt = 0; mt < 2; mt++) {
            int lr = l0 + m_base + mw2 + mt*16 + g;
            bool v0 = lr < LL, v1 = (lr + 8) < LL;
            #pragma unroll
            for (int nt = 0; nt < 4; nt++) {
                if (v0) {
                    mx[nt][0] = fmaxf(mx[nt][0], acc[mt][nt][0]);
                    mx[nt][1] = fmaxf(mx[nt][1], acc[mt][nt][1]);
                }
                if (v1) {
                    mx[nt][0] = fmaxf(mx[nt][0], acc[mt][nt][2]);
                    mx[nt][1] = fmaxf(mx[nt][1], acc[mt][nt][3]);
                }
            }
        }
        #pragma unroll
        for (int nt = 0; nt < 4; nt++) {
            #pragma unroll
            for (int j = 0; j < 2; j++) {
                float v = mx[nt][j];
                v = fmaxf(v, __shfl_xor_sync(0xffffffffu, v, 4));
                v = fmaxf(v, __shfl_xor_sync(0xffffffffu, v, 8));
                v = fmaxf(v, __shfl_xor_sync(0xffffffffu, v, 16));
                if (lane < 4)
                    atomicMaxFloat(&g_pmax[b*128 + nw4 + nt*8 + lane*2 + j],
                                   elu1(v + bias[nt][j]));
            }
        }
        p ^= 1;
    }
}

// ---------------- conv1 token tables ----------------
__global__ void k_tab(const float* __restrict__ Pe, const float* __restrict__ K1,
                      const float* __restrict__ bk1) {
    int idx = blockIdx.x * blockDim.x + threadIdx.x;
    if (idx >= 3*22*64) return;
    int o = idx & 63, r = idx >> 6;
    int t = r % 22, k = r / 22;
    float acc = (k == 1) ? bk1[o] : 0.f;
    #pragma unroll 8
    for (int i = 0; i < 64; i++) acc += Pe[t*64 + i] * K1[(o*64 + i)*3 + k];
    g_T[idx] = acc;
}

// ---------------- conv1 apply: writes fp16 directly ----------------
__global__ void __launch_bounds__(256) k_conv1_apply(const int* __restrict__ seq) {
    int b = blockIdx.y;
    int lofs = threadIdx.x >> 4, lq = threadIdx.x & 15;
    int l = blockIdx.x * 16 + lofs;
    if (l >= LL) return;
    int s1 = seq[b*LL + l];
    int c = lq * 4;
    float4 v = *reinterpret_cast<const float4*>(&g_T[(22 + s1)*64 + c]);
    if (l > 0) {
        int s0 = seq[b*LL + l - 1];
        float4 a = *reinterpret_cast<const float4*>(&g_T[s0*64 + c]);
        v.x += a.x; v.y += a.y; v.z += a.z; v.w += a.w;
    }
    if (l < LL-1) {
        int s2 = seq[b*LL + l + 1];
        float4 a = *reinterpret_cast<const float4*>(&g_T[(44 + s2)*64 + c]);
        v.x += a.x; v.y += a.y; v.z += a.z; v.w += a.w;
    }
    __half2 h0 = __floats2half2_rn(elu1(v.x), elu1(v.y));
    __half2 h1 = __floats2half2_rn(elu1(v.z), elu1(v.w));
    size_t base = ((size_t)b*LL + l)*64 + c;
    *reinterpret_cast<__half2*>(&g_p1h[base])     = h0;
    *reinterpret_cast<__half2*>(&g_p1h[base + 2]) = h1;
}

// ---------------- init ----------------
__global__ void k_init_prot() {
    int i = blockIdx.x * blockDim.x + threadIdx.x;
    if (i < NB*128) g_pmax[i] = -3.0e38f;
}

// ---------------- GAT1 GEMM + fused attention scalars (warp per node) ----------------
__global__ void k_gat1(const float* __restrict__ x, const float* __restrict__ W1,
                       const float* __restrict__ att_s, const float* __restrict__ att_d) {
    int gw = (blockIdx.x * blockDim.x + threadIdx.x) >> 5;
    int lane = threadIdx.x & 31;
    if (gw >= NN) return;
    float xv[5];
    #pragma unroll
    for (int f = 0; f < 5; f++) xv[f] = x[gw*5 + f];
    int c = lane * 4;
    float4 h;
    float* hp = reinterpret_cast<float*>(&h);
    #pragma unroll
    for (int j = 0; j < 4; j++) {
        float a = 0.f;
        #pragma unroll
        for (int f = 0; f < 5; f++) a += xv[f] * W1[f*128 + c + j];
        hp[j] = a;
    }
    *reinterpret_cast<float4*>(&g_h1[(size_t)gw*128 + c]) = h;
    float s = 0.f, d = 0.f;
    #pragma unroll
    for (int j = 0; j < 4; j++) { s += hp[j]*att_s[c + j]; d += hp[j]*att_d[c + j]; }
    float s0 = (lane < 16) ? s : 0.f, s1 = (lane < 16) ? 0.f : s;
    float d0 = (lane < 16) ? d : 0.f, d1 = (lane < 16) ? 0.f : d;
    s0 = warp_sum(s0); s1 = warp_sum(s1); d0 = warp_sum(d0); d1 = warp_sum(d1);
    if (lane == 0) {
        g_as1[gw*2] = s0; g_as1[gw*2+1] = s1;
        g_ad1[gw*2] = d0; g_ad1[gw*2+1] = d1;
    }
}

// ---------------- edge passes (softmax without max-shift: scores are O(1)) ----------------
template<int H>
__global__ void k_edge_den(const int* __restrict__ ei) {
    int e = blockIdx.x * blockDim.x + threadIdx.x;
    const int ET = NE + NN;
    if (e >= ET) return;
    int src, dst;
    if (e < NE) { src = ei[e]; dst = ei[NE + e]; } else { src = dst = e - NE; }
    const float* as_ = (H == 2) ? g_as1 : g_as2;
    const float* ad_ = (H == 2) ? g_ad1 : g_ad2;
    float* den_ = (H == 2) ? g_den1 : g_den2;
    float* e_ = (H == 2) ? g_e1 : g_e2;
    #pragma unroll
    for (int h = 0; h < H; h++) {
        float v = as_[src*H+h] + ad_[dst*H+h];
        v = v > 0.f ? v : 0.2f * v;
        float w = expf(v);
        e_[e*H+h] = w;
        atomicAdd(&den_[dst*H+h], w);
    }
}

template<int H>
__global__ void k_edge_acc(const int* __restrict__ ei) {
    int gw = (blockIdx.x * blockDim.x + threadIdx.x) >> 5;
    int lane = threadIdx.x & 31;
    const int ET = NE + NN;
    if (gw >= ET) return;
    int src, dst;
    if (gw < NE) { src = ei[gw]; dst = ei[NE + gw]; } else { src = dst = gw - NE; }
    const float* den_ = (H == 2) ? g_den1 : g_den2;
    const float* e_ = (H == 2) ? g_e1 : g_e2;
    const float* hin = (H == 2) ? g_h1 : g_h2;
    float* outp = (H == 2) ? g_out1 : g_out2;
    int h = (H == 2 && lane >= 16) ? 1 : 0;
    float alpha = e_[gw*H + h] / (den_[dst*H + h] + 1e-16f);
    float4 v = *reinterpret_cast<const float4*>(&hin[(size_t)src*128 + lane*4]);
    v.x *= alpha; v.y *= alpha; v.z *= alpha; v.w *= alpha;
    red_add_v4(&outp[(size_t)dst*128 + lane*4], v);
}

// ---------------- GAT2 GEMM (bias1+elu fused on A-load; att2 fused in epilogue) ----------------
__global__ void __launch_bounds__(256) k_gat2_mm(const float* __restrict__ W2,
                                                 const float* __restrict__ b1,
                                                 const float* __restrict__ att_s,
                                                 const float* __restrict__ att_d) {
    extern __shared__ float sm[];
    float* sg = sm;
    float* sw = sm + 64*128;
    int base = blockIdx.x * 64;
    int tid = threadIdx.x;
    for (int idx = tid; idx < 64*128; idx += 256)
        sg[idx] = elu1(g_out1[(size_t)base*128 + idx] + b1[idx & 127]);
    for (int idx = tid; idx < 128*128; idx += 256) sw[idx] = W2[idx];
    __syncthreads();
    int r0 = (tid >> 4) << 2;
    int c0 = (tid & 15) << 3;
    float acc[4][8];
    #pragma unroll
    for (int i = 0; i < 4; i++)
        #pragma unroll
        for (int j = 0; j < 8; j++) acc[i][j] = 0.f;
    #pragma unroll 4
    for (int k = 0; k < 128; k++) {
        float a[4];
        #pragma unroll
        for (int i = 0; i < 4; i++) a[i] = sg[(r0+i)*128 + k];
        float4 b0 = *reinterpret_cast<const float4*>(&sw[k*128 + c0]);
        float4 b1v = *reinterpret_cast<const float4*>(&sw[k*128 + c0 + 4]);
        #pragma unroll
        for (int i = 0; i < 4; i++) {
            acc[i][0] += a[i]*b0.x; acc[i][1] += a[i]*b0.y;
            acc[i][2] += a[i]*b0.z; acc[i][3] += a[i]*b0.w;
            acc[i][4] += a[i]*b1v.x; acc[i][5] += a[i]*b1v.y;
            acc[i][6] += a[i]*b1v.z; acc[i][7] += a[i]*b1v.w;
        }
    }
    #pragma unroll
    for (int i = 0; i < 4; i++) {
        float4 v0 = make_float4(acc[i][0], acc[i][1], acc[i][2], acc[i][3]);
        float4 v1 = make_float4(acc[i][4], acc[i][5], acc[i][6], acc[i][7]);
        *reinterpret_cast<float4*>(&g_h2[(size_t)(base+r0+i)*128 + c0]) = v0;
        *reinterpret_cast<float4*>(&g_h2[(size_t)(base+r0+i)*128 + c0 + 4]) = v1;
    }
    float ps[4], pd[4];
    #pragma unroll
    for (int i = 0; i < 4; i++) {
        float s = 0.f, d = 0.f;
        #pragma unroll
        for (int j = 0; j < 8; j++) {
            s += acc[i][j] * att_s[c0 + j];
            d += acc[i][j] * att_d[c0 + j];
        }
        ps[i] = s; pd[i] = d;
    }
    #pragma unroll
    for (int i = 0; i < 4; i++) {
        #pragma unroll
        for (int off = 8; off; off >>= 1) {
            ps[i] += __shfl_down_sync(0xffffffffu, ps[i], off, 16);
            pd[i] += __shfl_down_sync(0xffffffffu, pd[i], off, 16);
        }
    }
    if ((tid & 15) == 0) {
        #pragma unroll
        for (int i = 0; i < 4; i++) {
            g_as2[base + r0 + i] = ps[i];
            g_ad2[base + r0 + i] = pd[i];
        }
    }
}

// ---------------- pooling (bias2+elu fused) + dense ----------------
__global__ void k_pool(const int* __restrict__ batch, const float* __restrict__ b2) {
    int gw = (blockIdx.x * blockDim.x + threadIdx.x) >> 5;
    int lane = threadIdx.x & 31;
    if (gw >= NN) return;
    int g = batch[gw];
    int c = lane * 4;
    float4 v = *reinterpret_cast<const float4*>(&g_out2[(size_t)gw*128 + c]);
    v.x = elu1(v.x + b2[c]);
    v.y = elu1(v.y + b2[c+1]);
    v.z = elu1(v.z + b2[c+2]);
    v.w = elu1(v.w + b2[c+3]);
    red_add_v4(&g_sums[g*128 + c], v);
    if (lane == 0) atomicAdd(&g_cnt[g], 1.0f);
}

__global__ void k_drug(const float* __restrict__ Wd, const float* __restrict__ bd) {
    int idx = blockIdx.x * blockDim.x + threadIdx.x;
    if (idx >= NG*64) return;
    int g = idx >> 6, j4 = (idx & 63) * 4;
    float invc = 1.f / fmaxf(g_cnt[g], 1.f);
    const float* srow = g_sums + g*128;
    float4 a = make_float4(0.f, 0.f, 0.f, 0.f);
    #pragma unroll 8
    for (int k = 0; k < 128; k++) {
        float s = srow[k];
        float4 w = *reinterpret_cast<const float4*>(&Wd[k*256 + j4]);
        a.x += s*w.x; a.y += s*w.y; a.z += s*w.z; a.w += s*w.w;
    }
    float4 r;
    r.x = fmaxf(a.x * invc + bd[j4],     0.f);
    r.y = fmaxf(a.y * invc + bd[j4 + 1], 0.f);
    r.z = fmaxf(a.z * invc + bd[j4 + 2], 0.f);
    r.w = fmaxf(a.w * invc + bd[j4 + 3], 0.f);
    *reinterpret_cast<float4*>(&g_drug[g*256 + j4]) = r;
}

__global__ void k_prot(const float* __restrict__ Wp, const float* __restrict__ bp) {
    int idx = blockIdx.x * blockDim.x + threadIdx.x;
    if (idx >= NB*64) return;
    int g = idx >> 6, j4 = (idx & 63) * 4;
    const float* srow = g_pmax + g*128;
    float4 a = make_float4(0.f, 0.f, 0.f, 0.f);
    #pragma unroll 8
    for (int k = 0; k < 128; k++) {
        float s = srow[k];
        float4 w = *reinterpret_cast<const float4*>(&Wp[k*256 + j4]);
        a.x += s*w.x; a.y += s*w.y; a.z += s*w.z; a.w += s*w.w;
    }
    float4 r;
    r.x = fmaxf(a.x + bp[j4],     0.f);
    r.y = fmaxf(a.y + bp[j4 + 1], 0.f);
    r.z = fmaxf(a.z + bp[j4 + 2], 0.f);
    r.w = fmaxf(a.w + bp[j4 + 3], 0.f);
    *reinterpret_cast<float4*>(&g_prot[g*256 + j4]) = r;
}

// ---------------- head MLP ----------------
__global__ void __launch_bounds__(128) k_head(const float* __restrict__ Wf1, const float* __restrict__ bf1,
                                              const float* __restrict__ Wf2, const float* __restrict__ bf2,
                                              const float* __restrict__ Wo, const float* __restrict__ bo,
                                              float* __restrict__ out) {
    __shared__ float sh[512];
    __shared__ float s1[128];
    __shared__ float s2[64];
    int g = blockIdx.x, tid = threadIdx.x;
    for (int i = tid; i < 256; i += 128) {
        sh[i]       = g_drug[g*256 + i];
        sh[256 + i] = g_prot[g*256 + i];
    }
    __syncthreads();
    float acc = 0.f;
    #pragma unroll 8
    for (int k = 0; k < 512; k++) acc += sh[k] * Wf1[k*128 + tid];
    s1[tid] = fmaxf(acc + bf1[tid], 0.f);
    __syncthreads();
    if (tid < 64) {
        float a = 0.f;
        #pragma unroll 8
        for (int k = 0; k < 128; k++) a += s1[k] * Wf2[k*64 + tid];
        s2[tid] = fmaxf(a + bf2[tid], 0.f);
    }
    __syncthreads();
    if (tid < 32) {
        float a = s2[tid]*Wo[tid] + s2[tid+32]*Wo[tid+32];
        a = warp_sum(a);
        if (tid == 0) out[g] = a + bo[0];
    }
}

// ---------------- launch: protein branch forked onto a low-priority side stream ----------------
extern "C" void kernel_launch(void* const* d_in, const int* in_sizes, int n_in,
                              void* d_out, int out_size) {
    const float* x        = (const float*)d_in[0];
    const int*   ei       = (const int*)d_in[1];
    const int*   batch    = (const int*)d_in[2];
    const int*   seq      = (const int*)d_in[3];
    const float* W1       = (const float*)d_in[4];
    const float* att_s1   = (const float*)d_in[5];
    const float* att_d1   = (const float*)d_in[6];
    const float* b1       = (const float*)d_in[7];
    const float* W2       = (const float*)d_in[8];
    const float* att_s2   = (const float*)d_in[9];
    const float* att_d2   = (const float*)d_in[10];
    const float* b2       = (const float*)d_in[11];
    const float* Wd       = (const float*)d_in[12];
    const float* bd       = (const float*)d_in[13];
    const float* Pe       = (const float*)d_in[14];
    const float* K1       = (const float*)d_in[15];
    const float* bk1      = (const float*)d_in[16];
    const float* K2       = (const float*)d_in[17];
    const float* bk2      = (const float*)d_in[18];
    const float* Wp       = (const float*)d_in[19];
    const float* bp       = (const float*)d_in[20];
    const float* Wf1      = (const float*)d_in[21];
    const float* bf1      = (const float*)d_in[22];
    const float* Wf2      = (const float*)d_in[23];
    const float* bf2      = (const float*)d_in[24];
    const float* Wo       = (const float*)d_in[25];
    const float* bo       = (const float*)d_in[26];
    float* out = (float*)d_out;

    cudaFuncSetAttribute(k_gat2_mm,    cudaFuncAttributeMaxDynamicSharedMemorySize, 98304);
    cudaFuncSetAttribute(k_conv2_hmma, cudaFuncAttributeMaxDynamicSharedMemorySize, C2_SMEM);

    const int ET = NE + NN;

    int prLo = 0, prHi = 0;
    cudaDeviceGetStreamPriorityRange(&prLo, &prHi);
    cudaStream_t sp;
    cudaStreamCreateWithPriority(&sp, cudaStreamNonBlocking, prLo);  // protein = low priority
    cudaEvent_t e0, ep;
    cudaEventCreateWithFlags(&e0, cudaEventDisableTiming);
    cudaEventCreateWithFlags(&ep, cudaEventDisableTiming);

    cudaEventRecord(e0, 0);
    cudaStreamWaitEvent(sp, e0, 0);

    // ---- protein branch on sp ----
    k_init_prot<<<(NB*128 + 255)/256, 256, 0, sp>>>();
    k_bconv<<<(128*320 + 255)/256, 256, 0, sp>>>(K2);
    k_tab<<<17, 256, 0, sp>>>(Pe, K1, bk1);
    {
        dim3 grid((LL + 15)/16, NB);
        k_conv1_apply<<<grid, 256, 0, sp>>>(seq);
    }
    k_conv2_hmma<<<296, 256, C2_SMEM, sp>>>(bk2);
    k_prot<<<(NB*64 + 255)/256, 256, 0, sp>>>(Wp, bp);
    cudaEventRecord(ep, sp);

    // ---- drug branch on the default (capture) stream ----
    {
        void* p;
        cudaGetSymbolAddress(&p, g_out1);  cudaMemsetAsync(p, 0, sizeof(float)*NN*128, 0);
        cudaGetSymbolAddress(&p, g_out2);  cudaMemsetAsync(p, 0, sizeof(float)*NN*128, 0);
        cudaGetSymbolAddress(&p, g_den1);  cudaMemsetAsync(p, 0, sizeof(float)*NN*2, 0);
        cudaGetSymbolAddress(&p, g_den2);  cudaMemsetAsync(p, 0, sizeof(float)*NN, 0);
        cudaGetSymbolAddress(&p, g_sums);  cudaMemsetAsync(p, 0, sizeof(float)*NG*128, 0);
        cudaGetSymbolAddress(&p, g_cnt);   cudaMemsetAsync(p, 0, sizeof(float)*NG, 0);
    }
    k_gat1<<<(NN*32 + 255)/256, 256>>>(x, W1, att_s1, att_d1);
    k_edge_den<2><<<(ET + 255)/256, 256>>>(ei);
    k_edge_acc<2><<<(ET*32 + 255)/256, 256>>>(ei);
    k_gat2_mm<<<NN/64, 256, 98304>>>(W2, b1, att_s2, att_d2);
    k_edge_den<1><<<(ET + 255)/256, 256>>>(ei);
    k_edge_acc<1><<<(ET*32 + 255)/256, 256>>>(ei);
    k_pool<<<(NN*32 + 255)/256, 256>>>(batch, b2);
    k_drug<<<(NG*64 + 255)/256, 256>>>(Wd, bd);

    // join: head needs both branches
    cudaStreamWaitEvent(0, ep, 0);
    k_head<<<NG, 128>>>(Wf1, bf1, Wf2, bf2, Wo, bo, out);
}